// round 4
// baseline (speedup 1.0000x reference)
#include <cuda_runtime.h>
#include <math.h>

// ============================================================================
// DoubleLayer: fused 2-layer equivariant tensor-product MLP.
//   N=50000 rows; per row: 32 scalars + 16 vectors(3) -> 64 + 32 -> 32 + 16.
// Strategy:
//   * Pack weights once per launch (prep kernels) with all scale factors baked
//     in, svv/vsv merged, and scalar/gram pair symmetry folded (u<=v pairs).
//   * One fused main kernel: 64 rows per block; every contraction is a
//     shared-memory GEMM whose A matrix (per-row quadratic features) is
//     generated on the fly from per-row state held in shared memory.
//   * Accuracy: two-level accumulation (chunk-local regs -> persistent sum)
//     in all stages; Kahan-compensated cross-chunk sum in layer-2 stages.
// ============================================================================

#define NT  64     // rows per block
#define TPB 256

// K extents (padded to multiples of 32)
#define K1S      672   // layer1 scalar out: 528 sym xs-pairs + 136 sym gram pairs + 8 pad
#define K1S_REAL 664
#define K1S_SS   528
#define K1V      512   // layer1 vector out: 32x16 (merged svv+vsv)
#define K2S      2624  // layer2 scalar out: 2080 + 528 + 16 pad
#define K2S_REAL 2608
#define K2S_SS   2080
#define K2V      2048  // layer2 vector out: 64x32 (merged)

// ---- packed weights (static device globals; no dynamic allocation) ----
__device__ float  g_B1s[K1S * 64];
__device__ float  g_B1v[K1V * 32];
__device__ float  g_B2s[K2S * 32];
__device__ float  g_B2v[K2V * 16];
__device__ uchar2 g_T1[K1S];
__device__ uchar2 g_T2[K2S];

__device__ __forceinline__ float sigm(float a) { return 1.0f / (1.0f + expf(-a)); }

// Kahan update: sum += v with compensation c
__device__ __forceinline__ void kadd(float& sum, float& c, float v) {
  float y = v - c;
  float t = sum + y;
  c = (t - sum) - y;
  sum = t;
}

// ---------------------------------------------------------------------------
// Prep 1: pair index tables (u<=v enumeration, u-major)
// ---------------------------------------------------------------------------
__global__ void prep_tables_kernel() {
  for (int p = threadIdx.x; p < K1S; p += blockDim.x) {
    int u = 0, v = 0;
    if (p < K1S_SS)        { int q = p;            const int n = 32; while (q >= n - u) { q -= n - u; ++u; } v = u + q; }
    else if (p < K1S_REAL) { int q = p - K1S_SS;   const int n = 16; while (q >= n - u) { q -= n - u; ++u; } v = u + q; }
    g_T1[p] = make_uchar2((unsigned char)u, (unsigned char)v);
  }
  for (int p = threadIdx.x; p < K2S; p += blockDim.x) {
    int u = 0, v = 0;
    if (p < K2S_SS)        { int q = p;            const int n = 64; while (q >= n - u) { q -= n - u; ++u; } v = u + q; }
    else if (p < K2S_REAL) { int q = p - K2S_SS;   const int n = 32; while (q >= n - u) { q -= n - u; ++u; } v = u + q; }
    g_T2[p] = make_uchar2((unsigned char)u, (unsigned char)v);
  }
}

// ---------------------------------------------------------------------------
// Prep 2: pack + scale + symmetrize weights
// ---------------------------------------------------------------------------
__global__ void prep_pack_kernel(const float* __restrict__ Wsss1, const float* __restrict__ Wvvs1,
                                 const float* __restrict__ Wsvv1, const float* __restrict__ Wvsv1,
                                 const float* __restrict__ Wsss2, const float* __restrict__ Wvvs2,
                                 const float* __restrict__ Wsvv2, const float* __restrict__ Wvsv2) {
  const float INV3   = 0.57735026918962576f;     // 1/sqrt(3)
  const float pw1s   = 0.02795084971874737f;     // 1/sqrt(32^2+16^2)
  const float pw1sv  = pw1s * INV3;
  const float pw1v3  = 0.03125f;                 // sqrt(3/1024)/sqrt(3) = 1/32
  const float pw2s   = 0.013975424859373686f;    // 1/sqrt(64^2+32^2)
  const float pw2sv  = pw2s * INV3;
  const float pw2v3  = 0.015625f;                // sqrt(3/4096)/sqrt(3) = 1/64

  const int stride = gridDim.x * blockDim.x;
  const int t0 = blockIdx.x * blockDim.x + threadIdx.x;

  // B1s [K1S][64]
  for (int i = t0; i < K1S * 64; i += stride) {
    int p = i >> 6, w = i & 63;
    float val = 0.f;
    uchar2 t = g_T1[p];
    if (p < K1S_SS) {
      val = Wsss1[((int)t.x * 32 + (int)t.y) * 64 + w];
      if (t.x != t.y) val += Wsss1[((int)t.y * 32 + (int)t.x) * 64 + w];
      val *= pw1s;
    } else if (p < K1S_REAL) {
      val = Wvvs1[((int)t.x * 16 + (int)t.y) * 64 + w];
      if (t.x != t.y) val += Wvvs1[((int)t.y * 16 + (int)t.x) * 64 + w];
      val *= pw1sv;
    }
    g_B1s[i] = val;
  }
  // B1v [512][32], p = a*16+b
  for (int i = t0; i < K1V * 32; i += stride) {
    int p = i >> 5, w = i & 31;
    int a = p >> 4, b = p & 15;
    g_B1v[i] = pw1v3 * (Wsvv1[(a * 16 + b) * 32 + w] + Wvsv1[(b * 32 + a) * 32 + w]);
  }
  // B2s [K2S][32]
  for (int i = t0; i < K2S * 32; i += stride) {
    int p = i >> 5, w = i & 31;
    float val = 0.f;
    uchar2 t = g_T2[p];
    if (p < K2S_SS) {
      val = Wsss2[((int)t.x * 64 + (int)t.y) * 32 + w];
      if (t.x != t.y) val += Wsss2[((int)t.y * 64 + (int)t.x) * 32 + w];
      val *= pw2s;
    } else if (p < K2S_REAL) {
      val = Wvvs2[((int)t.x * 32 + (int)t.y) * 32 + w];
      if (t.x != t.y) val += Wvvs2[((int)t.y * 32 + (int)t.x) * 32 + w];
      val *= pw2sv;
    }
    g_B2s[i] = val;
  }
  // B2v [2048][16], p = a*32+b
  for (int i = t0; i < K2V * 16; i += stride) {
    int p = i >> 4, w = i & 15;
    int a = p >> 5, b = p & 31;
    g_B2v[i] = pw2v3 * (Wsvv2[(a * 32 + b) * 16 + w] + Wvsv2[(b * 64 + a) * 16 + w]);
  }
}

// ---------------------------------------------------------------------------
// Main fused kernel
// ---------------------------------------------------------------------------
// shared layout (floats), padded strides to kill bank conflicts
constexpr int OFF_XS = 0;                  // [64][33]
constexpr int OFF_XV = OFF_XS + 64 * 33;   // [64][51]  (16 vec * 3 comps, pad)
constexpr int OFF_HS = OFF_XV + 64 * 51;   // [64][65]
constexpr int OFF_HV = OFF_HS + 64 * 65;   // [64][97]  (32 vec * 3 comps, pad)
constexpr int OFF_A  = OFF_HV + 64 * 97;   // [32][192] max (also used as [32][64])
constexpr int OFF_B  = OFF_A + 32 * 192;   // [32][64] max
constexpr int SMEM_FLOATS = OFF_B + 32 * 64;
constexpr int SMEM_BYTES  = SMEM_FLOATS * 4;   // 95744

__global__ __launch_bounds__(TPB, 2)
void dl_main(const float* __restrict__ x, const float* __restrict__ b1,
             const float* __restrict__ b3, float* __restrict__ out, int nrows) {
  extern __shared__ float sm[];
  float* s_xs = sm + OFF_XS;
  float* s_xv = sm + OFF_XV;
  float* s_hs = sm + OFF_HS;
  float* s_hv = sm + OFF_HV;
  float* s_A  = sm + OFF_A;
  float* s_B  = sm + OFF_B;

  const int tid  = threadIdx.x;
  const int row0 = blockIdx.x * NT;

  // ---- load x (coalesced), reorder into xs / xv ----
  for (int e = tid; e < NT * 80; e += TPB) {
    int r = e / 80, c = e - r * 80;
    float v = (row0 + r < nrows) ? x[(size_t)(row0 + r) * 80 + c] : 0.f;
    if (c < 32) s_xs[r * 33 + c] = v;
    else        s_xv[r * 51 + (c - 32)] = v;   // c-32 == vec*3 + comp
  }
  __syncthreads();

  // ---- norm_act1: bias b1, no normalize ----
  for (int e = tid; e < NT * 32; e += TPB) {
    int r = e >> 5, c = e & 31;
    float v = s_xs[r * 33 + c];
    s_xs[r * 33 + c] = v * sigm(fabsf(v) + b1[c]);
  }
  for (int e = tid; e < NT * 16; e += TPB) {
    int r = e >> 4, b = e & 15;
    float* p = s_xv + r * 51 + b * 3;
    float v0 = p[0], v1 = p[1], v2 = p[2];
    float n = sqrtf(v0 * v0 + v1 * v1 + v2 * v2);
    float f = sigm(n + b1[32 + b]);
    p[0] = v0 * f; p[1] = v1 * f; p[2] = v2 * f;
  }
  __syncthreads();

  // ================= Stage S1s: hs[64r][64w], K=672 =================
  {
    float acc[4][4] = {};
    const int rg = tid & 15, wg = tid >> 4;
    const int r0 = rg * 4, w0 = wg * 4;
    for (int k0 = 0; k0 < K1S; k0 += 32) {
      for (int e = tid; e < 32 * 64; e += TPB) {
        int kk = e >> 6, r = e & 63;
        int k = k0 + kk;
        uchar2 t = g_T1[k];
        float a;
        if (k < K1S_SS) {
          a = s_xs[r * 33 + t.x] * s_xs[r * 33 + t.y];
        } else {
          const float* p1 = s_xv + r * 51 + (int)t.x * 3;
          const float* p2 = s_xv + r * 51 + (int)t.y * 3;
          a = p1[0] * p2[0] + p1[1] * p2[1] + p1[2] * p2[2];
        }
        s_A[kk * 64 + r] = a;
      }
      for (int e = tid; e < 512; e += TPB)
        ((float4*)s_B)[e] = ((const float4*)(g_B1s + k0 * 64))[e];
      __syncthreads();
      float ch[4][4] = {};
      #pragma unroll
      for (int kk = 0; kk < 32; ++kk) {
        float4 a4 = *(const float4*)(s_A + kk * 64 + r0);
        float4 b4 = *(const float4*)(s_B + kk * 64 + w0);
        const float ar[4] = {a4.x, a4.y, a4.z, a4.w};
        const float br[4] = {b4.x, b4.y, b4.z, b4.w};
        #pragma unroll
        for (int i = 0; i < 4; ++i)
          #pragma unroll
          for (int j = 0; j < 4; ++j)
            ch[i][j] = fmaf(ar[i], br[j], ch[i][j]);
      }
      #pragma unroll
      for (int i = 0; i < 4; ++i)
        #pragma unroll
        for (int j = 0; j < 4; ++j)
          acc[i][j] += ch[i][j];
      __syncthreads();
    }
    #pragma unroll
    for (int i = 0; i < 4; ++i)
      #pragma unroll
      for (int j = 0; j < 4; ++j)
        s_hs[(r0 + i) * 65 + (w0 + j)] = acc[i][j];
  }

  // ================= Stage S1v: hv[64r][32w][3], K=512, M=192 =================
  {
    float acc[12][2] = {};
    const int mg = tid & 15, wg = tid >> 4;
    const int m0 = mg * 12, w0 = wg * 2;
    for (int k0 = 0; k0 < K1V; k0 += 32) {
      for (int e = tid; e < 32 * 192; e += TPB) {
        int kk = e / 192, m = e - kk * 192;
        int k = k0 + kk;
        int a = k >> 4, b = k & 15;
        int r = m / 3, kc = m - r * 3;
        s_A[kk * 192 + m] = s_xs[r * 33 + a] * s_xv[r * 51 + b * 3 + kc];
      }
      ((float4*)s_B)[tid] = ((const float4*)(g_B1v + k0 * 32))[tid];  // 1024 floats
      __syncthreads();
      float ch[12][2] = {};
      #pragma unroll
      for (int kk = 0; kk < 32; ++kk) {
        float am[12];
        *(float4*)(am + 0) = *(const float4*)(s_A + kk * 192 + m0);
        *(float4*)(am + 4) = *(const float4*)(s_A + kk * 192 + m0 + 4);
        *(float4*)(am + 8) = *(const float4*)(s_A + kk * 192 + m0 + 8);
        float2 bb = *(const float2*)(s_B + kk * 32 + w0);
        #pragma unroll
        for (int i = 0; i < 12; ++i) {
          ch[i][0] = fmaf(am[i], bb.x, ch[i][0]);
          ch[i][1] = fmaf(am[i], bb.y, ch[i][1]);
        }
      }
      #pragma unroll
      for (int i = 0; i < 12; ++i) {
        acc[i][0] += ch[i][0];
        acc[i][1] += ch[i][1];
      }
      __syncthreads();
    }
    #pragma unroll
    for (int i = 0; i < 12; ++i) {
      int m = m0 + i, r = m / 3, kc = m - r * 3;
      s_hv[r * 97 + (w0 + 0) * 3 + kc] = acc[i][0];
      s_hv[r * 97 + (w0 + 1) * 3 + kc] = acc[i][1];
    }
  }
  __syncthreads();

  // ---- norm_act2: no bias, normalize=True ----
  for (int e = tid; e < NT * 64; e += TPB) {
    int r = e >> 6, c = e & 63;
    float v = s_hs[r * 65 + c];
    // v * sigmoid(|v|)/|v| == sign(v)*sigmoid(|v|)
    s_hs[r * 65 + c] = copysignf(sigm(fabsf(v)), v);
  }
  for (int e = tid; e < NT * 32; e += TPB) {
    int r = e >> 5, b = e & 31;
    float* p = s_hv + r * 97 + b * 3;
    float v0 = p[0], v1 = p[1], v2 = p[2];
    float n = sqrtf(v0 * v0 + v1 * v1 + v2 * v2);
    float f = (n > 0.f) ? (sigm(n) / n) : 0.f;
    p[0] = v0 * f; p[1] = v1 * f; p[2] = v2 * f;
  }
  __syncthreads();

  // ================= Stage S2s: os[64r][32w], K=2624 (into s_xs) =================
  {
    float acc[4][2] = {}, cmp[4][2] = {};
    const int rg = tid & 15, wg = tid >> 4;
    const int r0 = rg * 4, w0 = wg * 2;
    for (int k0 = 0; k0 < K2S; k0 += 32) {
      for (int e = tid; e < 32 * 64; e += TPB) {
        int kk = e >> 6, r = e & 63;
        int k = k0 + kk;
        uchar2 t = g_T2[k];
        float a;
        if (k < K2S_SS) {
          a = s_hs[r * 65 + t.x] * s_hs[r * 65 + t.y];
        } else {
          const float* p1 = s_hv + r * 97 + (int)t.x * 3;
          const float* p2 = s_hv + r * 97 + (int)t.y * 3;
          a = p1[0] * p2[0] + p1[1] * p2[1] + p1[2] * p2[2];
        }
        s_A[kk * 64 + r] = a;
      }
      ((float4*)s_B)[tid] = ((const float4*)(g_B2s + k0 * 32))[tid];  // 1024 floats
      __syncthreads();
      float ch[4][2] = {};
      #pragma unroll
      for (int kk = 0; kk < 32; ++kk) {
        float4 a4 = *(const float4*)(s_A + kk * 64 + r0);
        float2 bb = *(const float2*)(s_B + kk * 32 + w0);
        const float ar[4] = {a4.x, a4.y, a4.z, a4.w};
        #pragma unroll
        for (int i = 0; i < 4; ++i) {
          ch[i][0] = fmaf(ar[i], bb.x, ch[i][0]);
          ch[i][1] = fmaf(ar[i], bb.y, ch[i][1]);
        }
      }
      #pragma unroll
      for (int i = 0; i < 4; ++i) {
        kadd(acc[i][0], cmp[i][0], ch[i][0]);
        kadd(acc[i][1], cmp[i][1], ch[i][1]);
      }
      __syncthreads();
    }
    #pragma unroll
    for (int i = 0; i < 4; ++i) {
      s_xs[(r0 + i) * 33 + (w0 + 0)] = acc[i][0];
      s_xs[(r0 + i) * 33 + (w0 + 1)] = acc[i][1];
    }
  }

  // ================= Stage S2v: ov[64r][16w][3], K=2048, M=192 (into s_xv) ======
  {
    float acc[12] = {}, cmp[12] = {};
    const int mg = tid & 15, wg = tid >> 4;   // wg = output w (0..15)
    const int m0 = mg * 12;
    for (int k0 = 0; k0 < K2V; k0 += 32) {
      for (int e = tid; e < 32 * 192; e += TPB) {
        int kk = e / 192, m = e - kk * 192;
        int k = k0 + kk;
        int a = k >> 5, b = k & 31;
        int r = m / 3, kc = m - r * 3;
        s_A[kk * 192 + m] = s_hs[r * 65 + a] * s_hv[r * 97 + b * 3 + kc];
      }
      if (tid < 128)
        ((float4*)s_B)[tid] = ((const float4*)(g_B2v + k0 * 16))[tid];  // 512 floats
      __syncthreads();
      float ch[12] = {};
      #pragma unroll
      for (int kk = 0; kk < 32; ++kk) {
        float am[12];
        *(float4*)(am + 0) = *(const float4*)(s_A + kk * 192 + m0);
        *(float4*)(am + 4) = *(const float4*)(s_A + kk * 192 + m0 + 4);
        *(float4*)(am + 8) = *(const float4*)(s_A + kk * 192 + m0 + 8);
        float bb = s_B[kk * 16 + wg];
        #pragma unroll
        for (int i = 0; i < 12; ++i) ch[i] = fmaf(am[i], bb, ch[i]);
      }
      #pragma unroll
      for (int i = 0; i < 12; ++i) kadd(acc[i], cmp[i], ch[i]);
      __syncthreads();
    }
    #pragma unroll
    for (int i = 0; i < 12; ++i) {
      int m = m0 + i, r = m / 3, kc = m - r * 3;
      s_xv[r * 51 + wg * 3 + kc] = acc[i];
    }
  }
  __syncthreads();

  // ---- norm_act3 (bias b3, no normalize) + store ----
  for (int e = tid; e < NT * 32; e += TPB) {
    int r = e >> 5, c = e & 31;
    int gr = row0 + r;
    float v = s_xs[r * 33 + c];
    v = v * sigm(fabsf(v) + b3[c]);
    if (gr < nrows) out[(size_t)gr * 80 + c] = v;
  }
  for (int e = tid; e < NT * 16; e += TPB) {
    int r = e >> 4, b = e & 15;
    int gr = row0 + r;
    float* p = s_xv + r * 51 + b * 3;
    float v0 = p[0], v1 = p[1], v2 = p[2];
    float n = sqrtf(v0 * v0 + v1 * v1 + v2 * v2);
    float f = sigm(n + b3[32 + b]);
    if (gr < nrows) {
      out[(size_t)gr * 80 + 32 + b * 3 + 0] = v0 * f;
      out[(size_t)gr * 80 + 32 + b * 3 + 1] = v1 * f;
      out[(size_t)gr * 80 + 32 + b * 3 + 2] = v2 * f;
    }
  }
}

// ---------------------------------------------------------------------------
extern "C" void kernel_launch(void* const* d_in, const int* in_sizes, int n_in,
                              void* d_out, int out_size) {
  const float* x     = (const float*)d_in[0];
  const float* Wsss1 = (const float*)d_in[1];
  const float* Wvvs1 = (const float*)d_in[2];
  const float* Wsvv1 = (const float*)d_in[3];
  const float* Wvsv1 = (const float*)d_in[4];
  const float* Wsss2 = (const float*)d_in[5];
  const float* Wvvs2 = (const float*)d_in[6];
  const float* Wsvv2 = (const float*)d_in[7];
  const float* Wvsv2 = (const float*)d_in[8];
  const float* b1    = (const float*)d_in[9];
  const float* b3    = (const float*)d_in[10];
  float* out = (float*)d_out;

  const int nrows = in_sizes[0] / 80;

  cudaFuncSetAttribute(dl_main, cudaFuncAttributeMaxDynamicSharedMemorySize, SMEM_BYTES);

  prep_tables_kernel<<<1, 256>>>();
  prep_pack_kernel<<<176, 256>>>(Wsss1, Wvvs1, Wsvv1, Wvsv1, Wsss2, Wvvs2, Wsvv2, Wvsv2);

  const int grid = (nrows + NT - 1) / NT;
  dl_main<<<grid, TPB, SMEM_BYTES>>>(x, b1, b3, out, nrows);
}

// round 16
// speedup vs baseline: 2.5126x; 2.5126x over previous
#include <cuda_runtime.h>
#include <math.h>

// ============================================================================
// DoubleLayer: fused 2-layer equivariant tensor-product MLP.
//   N=50000 rows: 32 scalars + 16 vec(3) -> 64 + 32 -> 32 + 16.
// R8 = R5 (transposed [channel][row] features, shared pair tables, merged prep,
//      vectorized float4 scalar-stage fills, staged coalesced I/O)
//    + FACTORIZED vector stages:  zv[w,kc] = sum_b v[b,kc] * t[b,w],
//      t[b,w] = sum_a s[a]*W[a,b,w]   (GEMM-1 in registers, b-chunked),
//      cutting FMA/row 274k -> 185k.  Norms fused into writebacks.
// Scalar stages (incl. Kahan in S2s) keep R4-verified math.
// ============================================================================

#define NT  64     // rows per block
#define TPB 256

// K extents (padded to multiples of 32)
#define K1S      672   // layer1 scalar: 528 sym xs-pairs + 136 sym gram pairs + 8 pad
#define K1S_REAL 664
#define K1S_SS   528
#define K2S      2624  // layer2 scalar: 2080 + 528 + 16 pad
#define K2S_REAL 2608
#define K2S_SS   2080

// ---- packed weights (static device globals; no dynamic allocation) ----
__device__ float  g_B1s[K1S * 64];
__device__ float  g_B1v[32 * 512];    // [a][b*32+w]  a:32, b:16, w:32
__device__ float  g_B2s[K2S * 32];
__device__ float  g_B2v[64 * 512];    // [a][b*16+w]  a:64, b:32, w:16
__device__ uchar2 g_T1[K1S];
__device__ uchar2 g_T2[K2S];

__device__ __forceinline__ float sigm(float a) { return 1.0f / (1.0f + expf(-a)); }

// Kahan update: sum += v with compensation c
__device__ __forceinline__ void kadd(float& sum, float& c, float v) {
  float y = v - c;
  float t = sum + y;
  c = (t - sum) - y;
  sum = t;
}

// triangular pair enumeration: p -> (u, v), u<=v, u-major, n channels
__device__ __forceinline__ void tri_uv(int p, int n, int& u, int& v) {
  float fn = 2.0f * n + 1.0f;
  int uu = (int)((fn - sqrtf(fn * fn - 8.0f * (float)p)) * 0.5f);
  if (uu < 0) uu = 0;
  if (uu > n - 1) uu = n - 1;
  while (uu < n - 1 && ((uu + 1) * n - (((uu + 1) * uu) >> 1)) <= p) ++uu;
  while (uu > 0 && (uu * n - ((uu * (uu - 1)) >> 1)) > p) --uu;
  u = uu;
  v = uu + (p - (uu * n - ((uu * (uu - 1)) >> 1)));
}

// ---------------------------------------------------------------------------
// Prep: tables + pack + scale + symmetrize weights (single kernel)
// ---------------------------------------------------------------------------
__global__ void prep_pack_kernel(const float* __restrict__ Wsss1, const float* __restrict__ Wvvs1,
                                 const float* __restrict__ Wsvv1, const float* __restrict__ Wvsv1,
                                 const float* __restrict__ Wsss2, const float* __restrict__ Wvvs2,
                                 const float* __restrict__ Wsvv2, const float* __restrict__ Wvsv2) {
  const float INV3   = 0.57735026918962576f;     // 1/sqrt(3)
  const float pw1s   = 0.02795084971874737f;     // 1/sqrt(32^2+16^2)
  const float pw1sv  = pw1s * INV3;
  const float pw1v3  = 0.03125f;                 // 1/32
  const float pw2s   = 0.013975424859373686f;    // 1/sqrt(64^2+32^2)
  const float pw2sv  = pw2s * INV3;
  const float pw2v3  = 0.015625f;                // 1/64

  const int stride = gridDim.x * blockDim.x;
  const int t0 = blockIdx.x * blockDim.x + threadIdx.x;

  for (int p = t0; p < K1S; p += stride) {
    int u = 0, v = 0;
    if (p < K1S_SS)        tri_uv(p, 32, u, v);
    else if (p < K1S_REAL) tri_uv(p - K1S_SS, 16, u, v);
    g_T1[p] = make_uchar2((unsigned char)u, (unsigned char)v);
  }
  for (int p = t0; p < K2S; p += stride) {
    int u = 0, v = 0;
    if (p < K2S_SS)        tri_uv(p, 64, u, v);
    else if (p < K2S_REAL) tri_uv(p - K2S_SS, 32, u, v);
    g_T2[p] = make_uchar2((unsigned char)u, (unsigned char)v);
  }

  // B1s [K1S][64]
  for (int i = t0; i < K1S * 64; i += stride) {
    int p = i >> 6, w = i & 63;
    float val = 0.f;
    if (p < K1S_SS) {
      int u, v; tri_uv(p, 32, u, v);
      val = Wsss1[(u * 32 + v) * 64 + w];
      if (u != v) val += Wsss1[(v * 32 + u) * 64 + w];
      val *= pw1s;
    } else if (p < K1S_REAL) {
      int u, v; tri_uv(p - K1S_SS, 16, u, v);
      val = Wvvs1[(u * 16 + v) * 64 + w];
      if (u != v) val += Wvvs1[(v * 16 + u) * 64 + w];
      val *= pw1sv;
    }
    g_B1s[i] = val;
  }
  // B1v [a][b*32+w] == flat (a*16+b)*32+w
  for (int i = t0; i < 32 * 512; i += stride) {
    int p = i >> 5, w = i & 31;         // p = a*16+b
    int a = p >> 4, b = p & 15;
    g_B1v[i] = pw1v3 * (Wsvv1[(a * 16 + b) * 32 + w] + Wvsv1[(b * 32 + a) * 32 + w]);
  }
  // B2s [K2S][32]
  for (int i = t0; i < K2S * 32; i += stride) {
    int p = i >> 5, w = i & 31;
    float val = 0.f;
    if (p < K2S_SS) {
      int u, v; tri_uv(p, 64, u, v);
      val = Wsss2[(u * 64 + v) * 32 + w];
      if (u != v) val += Wsss2[(v * 64 + u) * 32 + w];
      val *= pw2s;
    } else if (p < K2S_REAL) {
      int u, v; tri_uv(p - K2S_SS, 32, u, v);
      val = Wvvs2[(u * 32 + v) * 32 + w];
      if (u != v) val += Wvvs2[(v * 32 + u) * 32 + w];
      val *= pw2sv;
    }
    g_B2s[i] = val;
  }
  // B2v [a][b*16+w] == flat (a*32+b)*16+w
  for (int i = t0; i < 64 * 512; i += stride) {
    int p = i >> 4, w = i & 15;         // p = a*32+b
    int a = p >> 5, b = p & 31;
    g_B2v[i] = pw2v3 * (Wsvv2[(a * 32 + b) * 16 + w] + Wvsv2[(b * 64 + a) * 16 + w]);
  }
}

// ---------------------------------------------------------------------------
// Main fused kernel — transposed feature layout: [channel][row], stride 64
// ---------------------------------------------------------------------------
constexpr int OFF_XST = 0;               // [32][64]  scalars (layer2 scalar out too)
constexpr int OFF_XVT = 2048;            // [48][64]  vec ch (b*3+c)
constexpr int OFF_HST = 5120;            // [64][64]  (normalized at writeback)
constexpr int OFF_HVT = 9216;            // [96][64]  (normalized at writeback)
constexpr int OFF_SCR = 15360;           // 8192-float scratch:
                                         //   scalar stages: A [0,2048) + B [2048,4096)
                                         //   vector stages: B-chunk [0,4096)
                                         //   output stage:  [64][81] = 5184
constexpr int SMEM_FLOATS = 23552;
constexpr int OFF_T1B = SMEM_FLOATS * 4;       // byte offset: 672 uchar2
constexpr int OFF_T2B = OFF_T1B + K1S * 2;     // 2624 uchar2
constexpr int SMEM_BYTES = OFF_T2B + K2S * 2;  // 100800 bytes

__global__ __launch_bounds__(TPB, 2)
void dl_main(const float* __restrict__ x, const float* __restrict__ b1,
             const float* __restrict__ b3, float* __restrict__ out, int nrows) {
  extern __shared__ float sm[];
  float* s_xsT = sm + OFF_XST;
  float* s_xvT = sm + OFF_XVT;
  float* s_hsT = sm + OFF_HST;
  float* s_hvT = sm + OFF_HVT;
  float* s_A   = sm + OFF_SCR;          // scalar-stage A
  float* s_B   = sm + OFF_SCR + 2048;   // scalar-stage B
  float* s_Bv  = sm + OFF_SCR;          // vector-stage B chunk
  uchar2* sh_T1 = (uchar2*)((char*)sm + OFF_T1B);
  uchar2* sh_T2 = (uchar2*)((char*)sm + OFF_T2B);

  const int tid  = threadIdx.x;
  const int row0 = blockIdx.x * NT;

  // ---- copy pair tables to shared ----
  {
    const unsigned int* gt1 = (const unsigned int*)g_T1;
    const unsigned int* gt2 = (const unsigned int*)g_T2;
    unsigned int* st1 = (unsigned int*)sh_T1;
    unsigned int* st2 = (unsigned int*)sh_T2;
    for (int i = tid; i < K1S / 2; i += TPB) st1[i] = gt1[i];
    for (int i = tid; i < K2S / 2; i += TPB) st2[i] = gt2[i];
  }

  // ---- load x (coalesced), transpose into xsT / xvT ----
  for (int e = tid; e < NT * 80; e += TPB) {
    int r = e / 80, c = e - r * 80;
    float v = (row0 + r < nrows) ? x[(size_t)(row0 + r) * 80 + c] : 0.f;
    if (c < 32) s_xsT[c * 64 + r] = v;
    else        s_xvT[(c - 32) * 64 + r] = v;   // c-32 == vec*3 + comp
  }
  __syncthreads();

  // ---- norm_act1: bias b1, no normalize ----
  for (int e = tid; e < NT * 32; e += TPB) {
    int c = e >> 6, r = e & 63;
    float v = s_xsT[c * 64 + r];
    s_xsT[c * 64 + r] = v * sigm(fabsf(v) + b1[c]);
  }
  for (int e = tid; e < 16 * 64; e += TPB) {
    int b = e >> 6, r = e & 63;
    float* p = s_xvT + b * 3 * 64 + r;
    float v0 = p[0], v1 = p[64], v2 = p[128];
    float n = sqrtf(v0 * v0 + v1 * v1 + v2 * v2);
    float f = sigm(n + b1[32 + b]);
    p[0] = v0 * f; p[64] = v1 * f; p[128] = v2 * f;
  }
  __syncthreads();

  // ================= Stage S1s: hs[64w][64r], K=672; normalize at writeback ====
  {
    float acc[4][4] = {};
    const int rg = tid & 15, wg = tid >> 4;
    const int r0 = rg * 4, w0 = wg * 4;
    for (int k0 = 0; k0 < K1S; k0 += 32) {
      for (int e2 = tid; e2 < 512; e2 += TPB) {
        int kk = e2 >> 4, r4 = (e2 & 15) << 2;
        int k = k0 + kk;
        uchar2 t = sh_T1[k];
        float4 a4;
        if (k < K1S_SS) {
          float4 u4 = *(const float4*)(s_xsT + (int)t.x * 64 + r4);
          float4 v4 = *(const float4*)(s_xsT + (int)t.y * 64 + r4);
          a4 = make_float4(u4.x * v4.x, u4.y * v4.y, u4.z * v4.z, u4.w * v4.w);
        } else {
          const float* pu = s_xvT + (int)t.x * 3 * 64 + r4;
          const float* pv = s_xvT + (int)t.y * 3 * 64 + r4;
          float4 u0 = *(const float4*)(pu),       v0 = *(const float4*)(pv);
          float4 u1 = *(const float4*)(pu + 64),  v1 = *(const float4*)(pv + 64);
          float4 u2 = *(const float4*)(pu + 128), v2 = *(const float4*)(pv + 128);
          a4.x = u0.x * v0.x + u1.x * v1.x + u2.x * v2.x;
          a4.y = u0.y * v0.y + u1.y * v1.y + u2.y * v2.y;
          a4.z = u0.z * v0.z + u1.z * v1.z + u2.z * v2.z;
          a4.w = u0.w * v0.w + u1.w * v1.w + u2.w * v2.w;
        }
        *(float4*)(s_A + kk * 64 + r4) = a4;
      }
      for (int e = tid; e < 512; e += TPB)
        ((float4*)s_B)[e] = ((const float4*)(g_B1s + k0 * 64))[e];
      __syncthreads();
      float ch[4][4] = {};
      #pragma unroll
      for (int kk = 0; kk < 32; ++kk) {
        float4 a4 = *(const float4*)(s_A + kk * 64 + r0);
        float4 b4 = *(const float4*)(s_B + kk * 64 + w0);
        const float ar[4] = {a4.x, a4.y, a4.z, a4.w};
        const float br[4] = {b4.x, b4.y, b4.z, b4.w};
        #pragma unroll
        for (int i = 0; i < 4; ++i)
          #pragma unroll
          for (int j = 0; j < 4; ++j)
            ch[i][j] = fmaf(ar[i], br[j], ch[i][j]);
      }
      #pragma unroll
      for (int i = 0; i < 4; ++i)
        #pragma unroll
        for (int j = 0; j < 4; ++j)
          acc[i][j] += ch[i][j];
      __syncthreads();
    }
    // writeback with norm_act2 scalar part fused: v*sigm(|v|)/|v| = copysign(sigm(|v|),v)
    #pragma unroll
    for (int i = 0; i < 4; ++i)
      #pragma unroll
      for (int j = 0; j < 4; ++j) {
        float v = acc[i][j];
        s_hsT[(w0 + j) * 64 + (r0 + i)] = copysignf(sigm(fabsf(v)), v);
      }
  }

  // ========== Stage S1v (FACTORIZED): hv[32w][3kc][64r] ==========
  //  t[b,w] = sum_a xs[a]*B1v[a][b*32+w]  (GEMM-1, regs);  hv += xv[b,kc]*t[b,w]
  //  b chunked by 2 (8 chunks). Normalize (norm_act2 vec) fused at writeback.
  {
    const int w  = tid & 31;       // output vector channel 0..31
    const int rg = tid >> 5;       // 0..7
    const int r0 = rg * 8;
    float acc0[8] = {}, acc1[8] = {}, acc2[8] = {};
    for (int c = 0; c < 8; ++c) {
      // stage B chunk [32a][64n], n = b_local*32 + w
      for (int e = tid; e < 512; e += TPB) {
        int a = e >> 4, q = e & 15;
        ((float4*)s_Bv)[e] = *(const float4*)(g_B1v + a * 512 + c * 64 + q * 4);
      }
      __syncthreads();
      // GEMM-1: t0 (b_local=0), t1 (b_local=1) for 8 rows
      float t0[8] = {}, t1[8] = {};
      #pragma unroll
      for (int a = 0; a < 32; ++a) {
        float4 A0 = *(const float4*)(s_xsT + a * 64 + r0);
        float4 A1 = *(const float4*)(s_xsT + a * 64 + r0 + 4);
        float B0 = s_Bv[a * 64 + w];
        float B1 = s_Bv[a * 64 + 32 + w];
        const float Ar[8] = {A0.x, A0.y, A0.z, A0.w, A1.x, A1.y, A1.z, A1.w};
        #pragma unroll
        for (int i = 0; i < 8; ++i) {
          t0[i] = fmaf(Ar[i], B0, t0[i]);
          t1[i] = fmaf(Ar[i], B1, t1[i]);
        }
      }
      // second contraction over the 2 b's in this chunk
      #pragma unroll
      for (int bl = 0; bl < 2; ++bl) {
        int b = c * 2 + bl;
        const float* tb = (bl == 0) ? t0 : t1;
        float4 X00 = *(const float4*)(s_xvT + (b * 3 + 0) * 64 + r0);
        float4 X01 = *(const float4*)(s_xvT + (b * 3 + 0) * 64 + r0 + 4);
        float4 X10 = *(const float4*)(s_xvT + (b * 3 + 1) * 64 + r0);
        float4 X11 = *(const float4*)(s_xvT + (b * 3 + 1) * 64 + r0 + 4);
        float4 X20 = *(const float4*)(s_xvT + (b * 3 + 2) * 64 + r0);
        float4 X21 = *(const float4*)(s_xvT + (b * 3 + 2) * 64 + r0 + 4);
        const float x0[8] = {X00.x, X00.y, X00.z, X00.w, X01.x, X01.y, X01.z, X01.w};
        const float x1[8] = {X10.x, X10.y, X10.z, X10.w, X11.x, X11.y, X11.z, X11.w};
        const float x2[8] = {X20.x, X20.y, X20.z, X20.w, X21.x, X21.y, X21.z, X21.w};
        #pragma unroll
        for (int i = 0; i < 8; ++i) {
          acc0[i] = fmaf(x0[i], tb[i], acc0[i]);
          acc1[i] = fmaf(x1[i], tb[i], acc1[i]);
          acc2[i] = fmaf(x2[i], tb[i], acc2[i]);
        }
      }
      __syncthreads();
    }
    // writeback with norm_act2 vector part fused
    #pragma unroll
    for (int i = 0; i < 8; ++i) {
      float v0 = acc0[i], v1 = acc1[i], v2 = acc2[i];
      float n = sqrtf(v0 * v0 + v1 * v1 + v2 * v2);
      float f = (n > 0.f) ? (sigm(n) / n) : 0.f;
      int r = r0 + i;
      s_hvT[(w * 3 + 0) * 64 + r] = v0 * f;
      s_hvT[(w * 3 + 1) * 64 + r] = v1 * f;
      s_hvT[(w * 3 + 2) * 64 + r] = v2 * f;
    }
  }
  __syncthreads();

  // ================= Stage S2s: os[32w][64r], K=2624 (into s_xsT) ===============
  {
    float acc[4][2] = {}, cmp[4][2] = {};
    const int rg = tid & 15, wg = tid >> 4;
    const int r0 = rg * 4, w0 = wg * 2;
    for (int k0 = 0; k0 < K2S; k0 += 32) {
      for (int e2 = tid; e2 < 512; e2 += TPB) {
        int kk = e2 >> 4, r4 = (e2 & 15) << 2;
        int k = k0 + kk;
        uchar2 t = sh_T2[k];
        float4 a4;
        if (k < K2S_SS) {
          float4 u4 = *(const float4*)(s_hsT + (int)t.x * 64 + r4);
          float4 v4 = *(const float4*)(s_hsT + (int)t.y * 64 + r4);
          a4 = make_float4(u4.x * v4.x, u4.y * v4.y, u4.z * v4.z, u4.w * v4.w);
        } else {
          const float* pu = s_hvT + (int)t.x * 3 * 64 + r4;
          const float* pv = s_hvT + (int)t.y * 3 * 64 + r4;
          float4 u0 = *(const float4*)(pu),       v0 = *(const float4*)(pv);
          float4 u1 = *(const float4*)(pu + 64),  v1 = *(const float4*)(pv + 64);
          float4 u2 = *(const float4*)(pu + 128), v2 = *(const float4*)(pv + 128);
          a4.x = u0.x * v0.x + u1.x * v1.x + u2.x * v2.x;
          a4.y = u0.y * v0.y + u1.y * v1.y + u2.y * v2.y;
          a4.z = u0.z * v0.z + u1.z * v1.z + u2.z * v2.z;
          a4.w = u0.w * v0.w + u1.w * v1.w + u2.w * v2.w;
        }
        *(float4*)(s_A + kk * 64 + r4) = a4;
      }
      ((float4*)s_B)[tid] = ((const float4*)(g_B2s + k0 * 32))[tid];  // 1024 floats
      __syncthreads();
      float ch[4][2] = {};
      #pragma unroll
      for (int kk = 0; kk < 32; ++kk) {
        float4 a4 = *(const float4*)(s_A + kk * 64 + r0);
        float2 bb = *(const float2*)(s_B + kk * 32 + w0);
        const float ar[4] = {a4.x, a4.y, a4.z, a4.w};
        #pragma unroll
        for (int i = 0; i < 4; ++i) {
          ch[i][0] = fmaf(ar[i], bb.x, ch[i][0]);
          ch[i][1] = fmaf(ar[i], bb.y, ch[i][1]);
        }
      }
      #pragma unroll
      for (int i = 0; i < 4; ++i) {
        kadd(acc[i][0], cmp[i][0], ch[i][0]);
        kadd(acc[i][1], cmp[i][1], ch[i][1]);
      }
      __syncthreads();
    }
    #pragma unroll
    for (int i = 0; i < 4; ++i) {
      s_xsT[(w0 + 0) * 64 + (r0 + i)] = acc[i][0];
      s_xsT[(w0 + 1) * 64 + (r0 + i)] = acc[i][1];
    }
  }

  // ========== Stage S2v (FACTORIZED): ov[16w][3kc][64r] ==========
  //  t[b,w] = sum_a hs[a]*B2v[a][b*16+w]; ov += hv[b,kc]*t[b,w]
  //  b chunked by 4 (8 chunks). K=64 split 32+32 (two-level).
  float ovacc0[4] = {}, ovacc1[4] = {}, ovacc2[4] = {};
  const int vw  = tid & 15;       // output vector channel 0..15
  const int vrg = tid >> 4;       // 0..15
  const int vr0 = vrg * 4;
  {
    for (int c = 0; c < 8; ++c) {
      // stage B chunk [64a][64n], n = b_local*16 + w
      for (int e = tid; e < 1024; e += TPB) {
        int a = e >> 4, q = e & 15;
        ((float4*)s_Bv)[e] = *(const float4*)(g_B2v + a * 512 + c * 64 + q * 4);
      }
      __syncthreads();
      float t[4][4] = {};   // [b_local][row]
      {
        float u[4][4] = {};
        #pragma unroll
        for (int a = 0; a < 32; ++a) {
          float4 A4 = *(const float4*)(s_hsT + a * 64 + vr0);
          const float Ar[4] = {A4.x, A4.y, A4.z, A4.w};
          #pragma unroll
          for (int bl = 0; bl < 4; ++bl) {
            float Bv = s_Bv[a * 64 + bl * 16 + vw];
            #pragma unroll
            for (int i = 0; i < 4; ++i) t[bl][i] = fmaf(Ar[i], Bv, t[bl][i]);
          }
        }
        #pragma unroll
        for (int a = 32; a < 64; ++a) {
          float4 A4 = *(const float4*)(s_hsT + a * 64 + vr0);
          const float Ar[4] = {A4.x, A4.y, A4.z, A4.w};
          #pragma unroll
          for (int bl = 0; bl < 4; ++bl) {
            float Bv = s_Bv[a * 64 + bl * 16 + vw];
            #pragma unroll
            for (int i = 0; i < 4; ++i) u[bl][i] = fmaf(Ar[i], Bv, u[bl][i]);
          }
        }
        #pragma unroll
        for (int bl = 0; bl < 4; ++bl)
          #pragma unroll
          for (int i = 0; i < 4; ++i) t[bl][i] += u[bl][i];
      }
      // second contraction over the 4 b's in this chunk
      #pragma unroll
      for (int bl = 0; bl < 4; ++bl) {
        int b = c * 4 + bl;
        float4 H0 = *(const float4*)(s_hvT + (b * 3 + 0) * 64 + vr0);
        float4 H1 = *(const float4*)(s_hvT + (b * 3 + 1) * 64 + vr0);
        float4 H2 = *(const float4*)(s_hvT + (b * 3 + 2) * 64 + vr0);
        const float h0[4] = {H0.x, H0.y, H0.z, H0.w};
        const float h1[4] = {H1.x, H1.y, H1.z, H1.w};
        const float h2[4] = {H2.x, H2.y, H2.z, H2.w};
        #pragma unroll
        for (int i = 0; i < 4; ++i) {
          ovacc0[i] = fmaf(h0[i], t[bl][i], ovacc0[i]);
          ovacc1[i] = fmaf(h1[i], t[bl][i], ovacc1[i]);
          ovacc2[i] = fmaf(h2[i], t[bl][i], ovacc2[i]);
        }
      }
      __syncthreads();
    }
  }
  // (last chunk's trailing sync guarantees all s_Bv reads done -> scratch reusable)

  // ---- norm_act3 + staging (scratch reused as [64 rows][81] stage buffer) ----
  float* s_stage = sm + OFF_SCR;
  // vector part directly from registers
  #pragma unroll
  for (int i = 0; i < 4; ++i) {
    float v0 = ovacc0[i], v1 = ovacc1[i], v2 = ovacc2[i];
    float n = sqrtf(v0 * v0 + v1 * v1 + v2 * v2);
    float f = sigm(n + b3[32 + vw]);
    int r = vr0 + i;
    s_stage[r * 81 + 32 + vw * 3 + 0] = v0 * f;
    s_stage[r * 81 + 32 + vw * 3 + 1] = v1 * f;
    s_stage[r * 81 + 32 + vw * 3 + 2] = v2 * f;
  }
  // scalar part from s_xsT
  for (int e = tid; e < 32 * 64; e += TPB) {
    int c = e >> 6, r = e & 63;
    float v = s_xsT[c * 64 + r];
    s_stage[r * 81 + c] = v * sigm(fabsf(v) + b3[c]);
  }
  __syncthreads();

  // ---- coalesced store ----
  for (int e = tid; e < NT * 80; e += TPB) {
    int r = e / 80, c = e - r * 80;
    int gr = row0 + r;
    if (gr < nrows) out[(size_t)gr * 80 + c] = s_stage[r * 81 + c];
  }
}

// ---------------------------------------------------------------------------
extern "C" void kernel_launch(void* const* d_in, const int* in_sizes, int n_in,
                              void* d_out, int out_size) {
  const float* x     = (const float*)d_in[0];
  const float* Wsss1 = (const float*)d_in[1];
  const float* Wvvs1 = (const float*)d_in[2];
  const float* Wsvv1 = (const float*)d_in[3];
  const float* Wvsv1 = (const float*)d_in[4];
  const float* Wsss2 = (const float*)d_in[5];
  const float* Wvvs2 = (const float*)d_in[6];
  const float* Wsvv2 = (const float*)d_in[7];
  const float* Wvsv2 = (const float*)d_in[8];
  const float* b1    = (const float*)d_in[9];
  const float* b3    = (const float*)d_in[10];
  float* out = (float*)d_out;

  const int nrows = in_sizes[0] / 80;

  cudaFuncSetAttribute(dl_main, cudaFuncAttributeMaxDynamicSharedMemorySize, SMEM_BYTES);

  prep_pack_kernel<<<176, 256>>>(Wsss1, Wvvs1, Wsvv1, Wvsv1, Wsss2, Wvvs2, Wsvv2, Wvsv2);

  const int grid = (nrows + NT - 1) / NT;
  dl_main<<<grid, TPB, SMEM_BYTES>>>(x, b1, b3, out, nrows);
}